// round 2
// baseline (speedup 1.0000x reference)
#include <cuda_runtime.h>
#include <math.h>

#define BATCH 512
#define MSIZE 4096
#define DDIM  64
#define CDIM  256
#define EPSF  1e-8f
#define NTHREADS 256

__device__ __forceinline__ float block_reduce_sum(float v, float* sbuf, int t) {
    #pragma unroll
    for (int o = 16; o > 0; o >>= 1) v += __shfl_xor_sync(0xffffffffu, v, o);
    if ((t & 31) == 0) sbuf[t >> 5] = v;
    __syncthreads();
    if (t < 8) {
        float x = sbuf[t];
        #pragma unroll
        for (int o = 4; o > 0; o >>= 1) x += __shfl_xor_sync(0xffu, x, o);
        if (t == 0) sbuf[0] = x;
    }
    __syncthreads();
    float r = sbuf[0];
    __syncthreads();
    return r;
}

__device__ __forceinline__ float block_reduce_max(float v, float* sbuf, int t) {
    #pragma unroll
    for (int o = 16; o > 0; o >>= 1) v = fmaxf(v, __shfl_xor_sync(0xffffffffu, v, o));
    if ((t & 31) == 0) sbuf[t >> 5] = v;
    __syncthreads();
    if (t < 8) {
        float x = sbuf[t];
        #pragma unroll
        for (int o = 4; o > 0; o >>= 1) x = fmaxf(x, __shfl_xor_sync(0xffu, x, o));
        if (t == 0) sbuf[0] = x;
    }
    __syncthreads();
    float r = sbuf[0];
    __syncthreads();
    return r;
}

__device__ __forceinline__ float softplusf(float x) {
    return (x > 20.0f) ? x : log1pf(expf(x));
}

__global__ __launch_bounds__(NTHREADS)
void ntm_head_kernel(const float* __restrict__ memory,
                     const float* __restrict__ cs_all,
                     const float* __restrict__ prev,
                     const float* __restrict__ Wk,
                     const float* __restrict__ Wb,    const float* __restrict__ bb,
                     const float* __restrict__ Wgate, const float* __restrict__ bgate,
                     const float* __restrict__ Ws,    const float* __restrict__ bs,
                     const float* __restrict__ Wg,    const float* __restrict__ bg,
                     float* __restrict__ out)
{
    __shared__ float s_cs[CDIM];
    __shared__ __align__(16) float s_q[DDIM];
    __shared__ float s_red[16];
    __shared__ float s_sim[MSIZE];
    __shared__ float s_g[MSIZE];

    const int b = blockIdx.x;
    const int t = threadIdx.x;

    // ---------------- Phase 0: load controller state ----------------
    s_cs[t] = cs_all[(size_t)b * CDIM + t];
    __syncthreads();

    // ---------------- Phase 1: small dots (each thread owns one c) ----
    const float csv = s_cs[t];
    float zb    = block_reduce_sum(csv * Wb[t],        s_red, t);
    float zgate = block_reduce_sum(csv * Wgate[t],     s_red, t);
    float zG    = block_reduce_sum(csv * Wg[t],        s_red, t);
    float z0    = block_reduce_sum(csv * Ws[t * 3 + 0], s_red, t);
    float z1    = block_reduce_sum(csv * Ws[t * 3 + 1], s_red, t);
    float z2    = block_reduce_sum(csv * Ws[t * 3 + 2], s_red, t);

    const float beta  = softplusf(zb + bb[0]) + 1.0f;
    const float gate  = 1.0f / (1.0f + expf(-(zgate + bgate[0])));
    const float gamma = softplusf(zG + bg[0]) + 1.0f;
    z0 += bs[0]; z1 += bs[1]; z2 += bs[2];
    {
        float zm = fmaxf(z0, fmaxf(z1, z2));
        z0 = expf(z0 - zm); z1 = expf(z1 - zm); z2 = expf(z2 - zm);
        float iz = 1.0f / (z0 + z1 + z2);
        z0 *= iz; z1 *= iz; z2 *= iz;
    }

    // ---------------- Phase 1b: query = cs @ Wk, then fold beta/norm --
    if (t < DDIM) {
        float acc = 0.0f;
        #pragma unroll 8
        for (int c = 0; c < CDIM; c++) acc = fmaf(s_cs[c], Wk[c * DDIM + t], acc);
        s_q[t] = acc;
    }
    // each t<64 reads back its own write: no sync needed before partial
    float lq = (t < DDIM) ? s_q[t] * s_q[t] : 0.0f;
    float qn2 = block_reduce_sum(lq, s_red, t);      // syncs inside
    const float qscale = beta / (sqrtf(qn2) + EPSF); // bq = beta * q / (||q||+eps)
    if (t < DDIM) s_q[t] *= qscale;
    __syncthreads();

    // ---------------- Phase 2: sim over M (HBM-bound main loop) -------
    const int lane = t & 31;
    const int l    = lane & 15;          // lane within 16-lane row group
    const int grp  = t >> 4;             // 0..15: row group id
    const float4 bq = ((const float4*)s_q)[l];
    const float4* mem4 = (const float4*)memory + ((size_t)b * MSIZE) * 16 + l;

    for (int r = grp; r < MSIZE; r += 64) {
        float4 v0 = __ldcs(&mem4[(size_t)(r      ) * 16]);
        float4 v1 = __ldcs(&mem4[(size_t)(r + 16 ) * 16]);
        float4 v2 = __ldcs(&mem4[(size_t)(r + 32 ) * 16]);
        float4 v3 = __ldcs(&mem4[(size_t)(r + 48 ) * 16]);

        float d0 = v0.x*bq.x + v0.y*bq.y + v0.z*bq.z + v0.w*bq.w;
        float n0 = v0.x*v0.x + v0.y*v0.y + v0.z*v0.z + v0.w*v0.w;
        float d1 = v1.x*bq.x + v1.y*bq.y + v1.z*bq.z + v1.w*bq.w;
        float n1 = v1.x*v1.x + v1.y*v1.y + v1.z*v1.z + v1.w*v1.w;
        float d2 = v2.x*bq.x + v2.y*bq.y + v2.z*bq.z + v2.w*bq.w;
        float n2 = v2.x*v2.x + v2.y*v2.y + v2.z*v2.z + v2.w*v2.w;
        float d3 = v3.x*bq.x + v3.y*bq.y + v3.z*bq.z + v3.w*bq.w;
        float n3 = v3.x*v3.x + v3.y*v3.y + v3.z*v3.z + v3.w*v3.w;

        #pragma unroll
        for (int o = 8; o > 0; o >>= 1) {
            d0 += __shfl_xor_sync(0xffffffffu, d0, o);
            n0 += __shfl_xor_sync(0xffffffffu, n0, o);
            d1 += __shfl_xor_sync(0xffffffffu, d1, o);
            n1 += __shfl_xor_sync(0xffffffffu, n1, o);
            d2 += __shfl_xor_sync(0xffffffffu, d2, o);
            n2 += __shfl_xor_sync(0xffffffffu, n2, o);
            d3 += __shfl_xor_sync(0xffffffffu, d3, o);
            n3 += __shfl_xor_sync(0xffffffffu, n3, o);
        }
        if (l == 0) {
            s_sim[r     ] = d0 / (sqrtf(n0) + EPSF);
            s_sim[r + 16] = d1 / (sqrtf(n1) + EPSF);
            s_sim[r + 32] = d2 / (sqrtf(n2) + EPSF);
            s_sim[r + 48] = d3 / (sqrtf(n3) + EPSF);
        }
    }
    __syncthreads();

    // ---------------- Phase 3: softmax over M -------------------------
    float lm = -1e30f;
    for (int j = t; j < MSIZE; j += NTHREADS) lm = fmaxf(lm, s_sim[j]);
    const float smax = block_reduce_max(lm, s_red, t);

    float ls = 0.0f;
    for (int j = t; j < MSIZE; j += NTHREADS) {
        float e = expf(s_sim[j] - smax);
        s_sim[j] = e;
        ls += e;
    }
    const float Z = block_reduce_sum(ls, s_red, t);

    // ---------------- Phase 4: gate blend with previous weights -------
    const float invZg = gate / Z;
    const float og = 1.0f - gate;
    const float* prow = prev + (size_t)b * MSIZE;
    for (int j = t; j < MSIZE; j += NTHREADS)
        s_g[j] = s_sim[j] * invZg + og * __ldg(&prow[j]);
    __syncthreads();

    // ---------------- Phase 5: circular conv + sharpen ----------------
    float lp = 0.0f;
    for (int j = t; j < MSIZE; j += NTHREADS) {
        float sh = s_g[(j - 1) & (MSIZE - 1)] * z0
                 + s_g[j]                     * z1
                 + s_g[(j + 1) & (MSIZE - 1)] * z2;
        float p = powf(sh + EPSF, gamma);
        s_sim[j] = p;
        lp += p;
    }
    const float P = block_reduce_sum(lp, s_red, t);

    // ---------------- Phase 6: final normalize + store ----------------
    const float inv = 1.0f / (P + EPSF);
    float* orow = out + (size_t)b * MSIZE;
    for (int j = t; j < MSIZE; j += NTHREADS) orow[j] = s_sim[j] * inv;
}

extern "C" void kernel_launch(void* const* d_in, const int* in_sizes, int n_in,
                              void* d_out, int out_size) {
    const float* memory = (const float*)d_in[0];
    const float* cs     = (const float*)d_in[1];
    const float* prev   = (const float*)d_in[2];
    const float* Wk     = (const float*)d_in[3];
    const float* Wb     = (const float*)d_in[4];
    const float* bb     = (const float*)d_in[5];
    const float* Wgate  = (const float*)d_in[6];
    const float* bgate  = (const float*)d_in[7];
    const float* Ws     = (const float*)d_in[8];
    const float* bs     = (const float*)d_in[9];
    const float* Wg     = (const float*)d_in[10];
    const float* bg     = (const float*)d_in[11];
    float* out = (float*)d_out;

    ntm_head_kernel<<<BATCH, NTHREADS>>>(memory, cs, prev, Wk, Wb, bb,
                                         Wgate, bgate, Ws, bs, Wg, bg, out);
}

// round 3
// speedup vs baseline: 1.0339x; 1.0339x over previous
#include <cuda_runtime.h>
#include <math.h>

#define BATCH 512
#define MSIZE 4096
#define DDIM  64
#define CDIM  256
#define EPSF  1e-8f
#define NTHREADS 256

__device__ __forceinline__ float block_reduce_sum(float v, float* sbuf, int t) {
    #pragma unroll
    for (int o = 16; o > 0; o >>= 1) v += __shfl_xor_sync(0xffffffffu, v, o);
    if ((t & 31) == 0) sbuf[t >> 5] = v;
    __syncthreads();
    if (t < 8) {
        float x = sbuf[t];
        #pragma unroll
        for (int o = 4; o > 0; o >>= 1) x += __shfl_xor_sync(0xffu, x, o);
        if (t == 0) sbuf[0] = x;
    }
    __syncthreads();
    float r = sbuf[0];
    __syncthreads();
    return r;
}

__device__ __forceinline__ float block_reduce_max(float v, float* sbuf, int t) {
    #pragma unroll
    for (int o = 16; o > 0; o >>= 1) v = fmaxf(v, __shfl_xor_sync(0xffffffffu, v, o));
    if ((t & 31) == 0) sbuf[t >> 5] = v;
    __syncthreads();
    if (t < 8) {
        float x = sbuf[t];
        #pragma unroll
        for (int o = 4; o > 0; o >>= 1) x = fmaxf(x, __shfl_xor_sync(0xffu, x, o));
        if (t == 0) sbuf[0] = x;
    }
    __syncthreads();
    float r = sbuf[0];
    __syncthreads();
    return r;
}

__device__ __forceinline__ float softplusf(float x) {
    return (x > 20.0f) ? x : log1pf(expf(x));
}

__device__ __forceinline__ float dot4(float4 a, float4 b) {
    return a.x*b.x + a.y*b.y + a.z*b.z + a.w*b.w;
}

__global__ __launch_bounds__(NTHREADS)
void ntm_head_kernel(const float* __restrict__ memory,
                     const float* __restrict__ cs_all,
                     const float* __restrict__ prev,
                     const float* __restrict__ Wk,
                     const float* __restrict__ Wb,    const float* __restrict__ bb,
                     const float* __restrict__ Wgate, const float* __restrict__ bgate,
                     const float* __restrict__ Ws,    const float* __restrict__ bs,
                     const float* __restrict__ Wg,    const float* __restrict__ bg,
                     float* __restrict__ out)
{
    __shared__ float s_cs[CDIM];
    __shared__ __align__(16) float s_q[DDIM];
    __shared__ float s_red[16];
    __shared__ float s_sim[MSIZE];
    __shared__ float s_g[MSIZE];

    const int b = blockIdx.x;
    const int t = threadIdx.x;

    // ---------------- Phase 0: load controller state ----------------
    s_cs[t] = cs_all[(size_t)b * CDIM + t];
    __syncthreads();

    // ---------------- Phase 1: small dots ----------------------------
    const float csv = s_cs[t];
    float zb    = block_reduce_sum(csv * Wb[t],         s_red, t);
    float zgate = block_reduce_sum(csv * Wgate[t],      s_red, t);
    float zG    = block_reduce_sum(csv * Wg[t],         s_red, t);
    float z0    = block_reduce_sum(csv * Ws[t * 3 + 0], s_red, t);
    float z1    = block_reduce_sum(csv * Ws[t * 3 + 1], s_red, t);
    float z2    = block_reduce_sum(csv * Ws[t * 3 + 2], s_red, t);

    const float beta  = softplusf(zb + bb[0]) + 1.0f;
    const float gate  = 1.0f / (1.0f + __expf(-(zgate + bgate[0])));
    const float gamma = softplusf(zG + bg[0]) + 1.0f;
    z0 += bs[0]; z1 += bs[1]; z2 += bs[2];
    {
        float zm = fmaxf(z0, fmaxf(z1, z2));
        z0 = __expf(z0 - zm); z1 = __expf(z1 - zm); z2 = __expf(z2 - zm);
        float iz = 1.0f / (z0 + z1 + z2);
        z0 *= iz; z1 *= iz; z2 *= iz;
    }

    // ---------------- Phase 1b: query = cs @ Wk, fold beta/norm -------
    if (t < DDIM) {
        float acc = 0.0f;
        #pragma unroll 8
        for (int c = 0; c < CDIM; c++) acc = fmaf(s_cs[c], Wk[c * DDIM + t], acc);
        s_q[t] = acc;
    }
    float lq = (t < DDIM) ? s_q[t] * s_q[t] : 0.0f;
    float qn2 = block_reduce_sum(lq, s_red, t);
    const float qscale = beta / (sqrtf(qn2) + EPSF);
    if (t < DDIM) s_q[t] *= qscale;
    __syncthreads();

    // ---------------- Phase 2: sim over M (HBM-bound main loop) -------
    // 8 lanes per row: lane = sr*8 + h; each thread loads 2 float4 from its
    // row (idx h and h+8). Each LDG.128 covers 4 full 128B lines (coalesced).
    // 4 row-chunks unrolled -> 8 LDG.128 in flight per thread.
    {
        const int wid  = t >> 5;
        const int lane = t & 31;
        const int sr   = lane >> 3;       // 0..3 : row within warp chunk
        const int h    = lane & 7;        // 0..7 : float4 slot within row half
        const float4* q4 = (const float4*)s_q;
        const float4 bqa = q4[h];
        const float4 bqb = q4[h + 8];
        const float4* mem4 = (const float4*)memory + (size_t)b * MSIZE * 16 + h;

        // warp chunk c covers rows: iter*128 + c*32 + wid*4 + sr
        for (int it = 0; it < MSIZE; it += 128) {
            const int r0 = it + wid * 4 + sr;

            const float4* p0 = mem4 + (size_t)(r0      ) * 16;
            const float4* p1 = mem4 + (size_t)(r0 + 32 ) * 16;
            const float4* p2 = mem4 + (size_t)(r0 + 64 ) * 16;
            const float4* p3 = mem4 + (size_t)(r0 + 96 ) * 16;

            float4 a0 = __ldcs(p0), a1 = __ldcs(p0 + 8);
            float4 b0 = __ldcs(p1), b1 = __ldcs(p1 + 8);
            float4 c0 = __ldcs(p2), c1 = __ldcs(p2 + 8);
            float4 e0 = __ldcs(p3), e1 = __ldcs(p3 + 8);

            float d0 = dot4(a0, bqa) + dot4(a1, bqb);
            float n0 = dot4(a0, a0)  + dot4(a1, a1);
            float d1 = dot4(b0, bqa) + dot4(b1, bqb);
            float n1 = dot4(b0, b0)  + dot4(b1, b1);
            float d2 = dot4(c0, bqa) + dot4(c1, bqb);
            float n2 = dot4(c0, c0)  + dot4(c1, c1);
            float d3 = dot4(e0, bqa) + dot4(e1, bqb);
            float n3 = dot4(e0, e0)  + dot4(e1, e1);

            #pragma unroll
            for (int o = 4; o > 0; o >>= 1) {
                d0 += __shfl_xor_sync(0xffffffffu, d0, o);
                n0 += __shfl_xor_sync(0xffffffffu, n0, o);
                d1 += __shfl_xor_sync(0xffffffffu, d1, o);
                n1 += __shfl_xor_sync(0xffffffffu, n1, o);
                d2 += __shfl_xor_sync(0xffffffffu, d2, o);
                n2 += __shfl_xor_sync(0xffffffffu, n2, o);
                d3 += __shfl_xor_sync(0xffffffffu, d3, o);
                n3 += __shfl_xor_sync(0xffffffffu, n3, o);
            }
            if (h == 0) {
                s_sim[r0     ] = d0 * rsqrtf(n0 + 1e-16f);
                s_sim[r0 + 32] = d1 * rsqrtf(n1 + 1e-16f);
                s_sim[r0 + 64] = d2 * rsqrtf(n2 + 1e-16f);
                s_sim[r0 + 96] = d3 * rsqrtf(n3 + 1e-16f);
            }
        }
    }
    __syncthreads();

    // ---------------- Phase 3: softmax over M -------------------------
    float lm = -1e30f;
    for (int j = t; j < MSIZE; j += NTHREADS) lm = fmaxf(lm, s_sim[j]);
    const float smax = block_reduce_max(lm, s_red, t);

    float ls = 0.0f;
    for (int j = t; j < MSIZE; j += NTHREADS) {
        float e = __expf(s_sim[j] - smax);
        s_sim[j] = e;
        ls += e;
    }
    const float Z = block_reduce_sum(ls, s_red, t);

    // ---------------- Phase 4: gate blend with previous weights -------
    const float invZg = gate / Z;
    const float og = 1.0f - gate;
    const float* prow = prev + (size_t)b * MSIZE;
    for (int j = t; j < MSIZE; j += NTHREADS)
        s_g[j] = s_sim[j] * invZg + og * __ldcs(&prow[j]);
    __syncthreads();

    // ---------------- Phase 5: circular conv + sharpen ----------------
    float lp = 0.0f;
    for (int j = t; j < MSIZE; j += NTHREADS) {
        float sh = s_g[(j - 1) & (MSIZE - 1)] * z0
                 + s_g[j]                     * z1
                 + s_g[(j + 1) & (MSIZE - 1)] * z2;
        float p = __powf(sh + EPSF, gamma);
        s_sim[j] = p;
        lp += p;
    }
    const float P = block_reduce_sum(lp, s_red, t);

    // ---------------- Phase 6: final normalize + store ----------------
    const float inv = 1.0f / (P + EPSF);
    float* orow = out + (size_t)b * MSIZE;
    for (int j = t; j < MSIZE; j += NTHREADS) __stcs(&orow[j], s_sim[j] * inv);
}

extern "C" void kernel_launch(void* const* d_in, const int* in_sizes, int n_in,
                              void* d_out, int out_size) {
    const float* memory = (const float*)d_in[0];
    const float* cs     = (const float*)d_in[1];
    const float* prev   = (const float*)d_in[2];
    const float* Wk     = (const float*)d_in[3];
    const float* Wb     = (const float*)d_in[4];
    const float* bb     = (const float*)d_in[5];
    const float* Wgate  = (const float*)d_in[6];
    const float* bgate  = (const float*)d_in[7];
    const float* Ws     = (const float*)d_in[8];
    const float* bs     = (const float*)d_in[9];
    const float* Wg     = (const float*)d_in[10];
    const float* bg     = (const float*)d_in[11];
    float* out = (float*)d_out;

    ntm_head_kernel<<<BATCH, NTHREADS>>>(memory, cs, prev, Wk, Wb, bb,
                                         Wgate, bgate, Ws, bs, Wg, bg, out);
}